// round 11
// baseline (speedup 1.0000x reference)
#include <cuda_runtime.h>

// FourierConv2D via DFT-as-GEMM with five symmetry folds (~6.4 GFLOP):
//  1) real input => only ky=0..255 of the 511-row spectrum
//  2) forward col-DFT: P/Q shared-product pairs give F(kx), F(511-kx) together
//  3) inverse col-DFT K-fold: S=G+G', D=G-G' => K=256
//  4) inverse col-DFT x-fold: distinct x=0..127 (+tail 128/129), partner 257-t
//  5) row-inverse y-fold: distinct y=0..127 (+tail 128/129)
// R11: stage4 moved to tensor pipe: mma.sync.m16n8k4 tf32 with 2xtf32 split
// (hi=cvt.rna.tf32(x), lo=cvt.rna.tf32(x-hi); products hh+hl+lh => fp32-grade).

namespace {
constexpr int N5    = 511;
constexpr int HH    = 256;
constexpr int NB    = 4;
constexpr int NCIN  = 4;
constexpr int NCOUT = 8;
constexpr int PLANE = N5 * N5;
constexpr int SQ    = HH * HH;       // 65536
constexpr int BC    = NB * NCIN;     // 16
constexpr int BO    = NB * NCOUT;    // 32
}

// ---- scratch (device globals) ----
__device__ float  g_Ar[SQ],  g_Ai[SQ];   // A[kx][n] = exp(-2pi i kx n/511)
__device__ float2 g_E[SQ];               // {Er,Ei}[x][kx] = exp(+2pi i kx (x+127)/511)/511
__device__ __align__(16) float g_Erh[SQ], g_Erl[SQ], g_Eih[SQ], g_Eil[SQ];  // tf32 splits of E
__device__ float  g_E5r[SQ], g_E5i[SQ];  // E5[y][ky] = w(ky) exp(+2pi i ky (y+127)/511)
__device__ float  g_T1r[BC*SQ], g_T1i[BC*SQ];
__device__ float2 g_P[BC*SQ], g_Q[BC*SQ];   // F(kx), F(511-kx), kx=0..255
__device__ float4 g_SD[BO*SQ];              // {Sr,Si,Dr,Di}[ky][kx]
__device__ float  g_T2r[BO*SQ], g_T2i[BO*SQ];

// ---- tf32 split helper: x = hi + lo with both exactly tf32 ----
__device__ __forceinline__ void split_tf32(float x, float &h, float &l) {
    unsigned xh, xl;
    asm("cvt.rna.tf32.f32 %0, %1;" : "=r"(xh) : "r"(__float_as_uint(x)));
    float hf = __uint_as_float(xh);
    asm("cvt.rna.tf32.f32 %0, %1;" : "=r"(xl) : "r"(__float_as_uint(x - hf)));
    h = hf; l = __uint_as_float(xl);
}

#define MMA_TF32_K4(D, A0, A1, B) \
    asm volatile("mma.sync.aligned.m16n8k4.row.col.f32.tf32.tf32.f32 " \
                 "{%0,%1,%2,%3}, {%4,%5}, {%6}, {%0,%1,%2,%3};" \
                 : "+f"(D[0]), "+f"(D[1]), "+f"(D[2]), "+f"(D[3]) \
                 : "r"(A0), "r"(A1), "r"(B))

// ---- twiddle init ----
__global__ void k_twiddle() {
    const int idx = blockIdx.x * blockDim.x + threadIdx.x;   // 0..65535
    const float TWO_PI = 6.283185307179586f;
    const int r = idx >> 8, c = idx & 255;
    {   int m = (r * c) % N5;
        float s, co; sincosf(TWO_PI * (float)m / (float)N5, &s, &co);
        g_Ar[idx] = co;  g_Ai[idx] = -s;
    }
    {   int m = (c * (r + 127)) % N5;
        float s, co; sincosf(TWO_PI * (float)m / (float)N5, &s, &co);
        const float inv = 1.0f / (float)N5;
        const float er = co * inv, ei = s * inv;
        g_E[idx] = make_float2(er, ei);
        float h, l;
        split_tf32(er, h, l); g_Erh[idx] = h; g_Erl[idx] = l;
        split_tf32(ei, h, l); g_Eih[idx] = h; g_Eil[idx] = l;
    }
    {   int m = (c * (r + 127)) % N5;
        float s, co; sincosf(TWO_PI * (float)m / (float)N5, &s, &co);
        const float w = (c == 0) ? (1.0f / (float)N5) : (2.0f / (float)N5);
        g_E5r[idx] = co * w;  g_E5i[idx] = s * w;
    }
}

// ---- stage 1: T1[z] (256x256 cplx) = A[0:256] (cplx) @ X[z] (256x256 real) ----
__global__ void __launch_bounds__(128) k_stage1(const float* __restrict__ im) {
    const int z = blockIdx.z;
    const float* __restrict__ X = im + (size_t)z * SQ;
    float* __restrict__ Cr = g_T1r + (size_t)z * SQ;
    float* __restrict__ Ci = g_T1i + (size_t)z * SQ;

    __shared__ float Asr[16][36], Asi[16][36], Bs[16][36];
    const int tid = threadIdx.x;
    const int tx = tid & 15, ty = tid >> 4;
    const int m0 = blockIdx.y * 32, n0 = blockIdx.x * 32;
    const int ra = tid >> 2, ka = (tid & 3) * 4;
    const int kb = tid >> 3, nb = (tid & 7) * 4;

    float cr[4][2] = {}, ci[4][2] = {};

    for (int k0 = 0; k0 < HH; k0 += 16) {
        float4 arv = *reinterpret_cast<const float4*>(g_Ar + (size_t)(m0 + ra)*HH + k0 + ka);
        float4 aiv = *reinterpret_cast<const float4*>(g_Ai + (size_t)(m0 + ra)*HH + k0 + ka);
        float4 bv  = *reinterpret_cast<const float4*>(X + (size_t)(k0 + kb)*HH + n0 + nb);
        Asr[ka+0][ra]=arv.x; Asr[ka+1][ra]=arv.y; Asr[ka+2][ra]=arv.z; Asr[ka+3][ra]=arv.w;
        Asi[ka+0][ra]=aiv.x; Asi[ka+1][ra]=aiv.y; Asi[ka+2][ra]=aiv.z; Asi[ka+3][ra]=aiv.w;
        Bs[kb][nb+0]=bv.x; Bs[kb][nb+1]=bv.y; Bs[kb][nb+2]=bv.z; Bs[kb][nb+3]=bv.w;
        __syncthreads();

        #pragma unroll 4
        for (int k = 0; k < 16; k++) {
            float4 a_r = *reinterpret_cast<const float4*>(&Asr[k][ty*4]);
            float4 a_i = *reinterpret_cast<const float4*>(&Asi[k][ty*4]);
            float2 b   = *reinterpret_cast<const float2*>(&Bs[k][tx*2]);
            const float ar[4] = {a_r.x, a_r.y, a_r.z, a_r.w};
            const float ai[4] = {a_i.x, a_i.y, a_i.z, a_i.w};
            const float bb[2] = {b.x, b.y};
            #pragma unroll
            for (int i = 0; i < 4; i++)
                #pragma unroll
                for (int j = 0; j < 2; j++) {
                    cr[i][j] += ar[i] * bb[j];
                    ci[i][j] += ai[i] * bb[j];
                }
        }
        __syncthreads();
    }
    const int gn = n0 + tx*2;
    #pragma unroll
    for (int i = 0; i < 4; i++) {
        const int gm = m0 + ty*4 + i;
        *reinterpret_cast<float2*>(Cr + (size_t)gm*HH + gn) = make_float2(cr[i][0], cr[i][1]);
        *reinterpret_cast<float2*>(Ci + (size_t)gm*HH + gn) = make_float2(ci[i][0], ci[i][1]);
    }
}

// ---- stage 2: P,Q[z][ky][kx] via shared products U/V/X/Y ----
__global__ void __launch_bounds__(128) k_stage2() {
    const int z = blockIdx.z;
    const float* __restrict__ T1r = g_T1r + (size_t)z * SQ;
    const float* __restrict__ T1i = g_T1i + (size_t)z * SQ;
    float2* __restrict__ P = g_P + (size_t)z * SQ;
    float2* __restrict__ Q = g_Q + (size_t)z * SQ;

    __shared__ float Asr[16][36], Asi[16][36], Bsr[16][36], Bsi[16][36];
    const int tid = threadIdx.x;
    const int tx = tid & 15, ty = tid >> 4;
    const int m0 = blockIdx.y * 32, n0 = blockIdx.x * 32;
    const int ra = tid >> 2, ka = (tid & 3) * 4;

    float U[4][2] = {}, V[4][2] = {}, Xc[4][2] = {}, Yc[4][2] = {};

    for (int k0 = 0; k0 < HH; k0 += 16) {
        float4 arv = *reinterpret_cast<const float4*>(T1r + (size_t)(m0 + ra)*HH + k0 + ka);
        float4 aiv = *reinterpret_cast<const float4*>(T1i + (size_t)(m0 + ra)*HH + k0 + ka);
        float4 brv = *reinterpret_cast<const float4*>(g_Ar + (size_t)(n0 + ra)*HH + k0 + ka);
        float4 biv = *reinterpret_cast<const float4*>(g_Ai + (size_t)(n0 + ra)*HH + k0 + ka);
        Asr[ka+0][ra]=arv.x; Asr[ka+1][ra]=arv.y; Asr[ka+2][ra]=arv.z; Asr[ka+3][ra]=arv.w;
        Asi[ka+0][ra]=aiv.x; Asi[ka+1][ra]=aiv.y; Asi[ka+2][ra]=aiv.z; Asi[ka+3][ra]=aiv.w;
        Bsr[ka+0][ra]=brv.x; Bsr[ka+1][ra]=brv.y; Bsr[ka+2][ra]=brv.z; Bsr[ka+3][ra]=brv.w;
        Bsi[ka+0][ra]=biv.x; Bsi[ka+1][ra]=biv.y; Bsi[ka+2][ra]=biv.z; Bsi[ka+3][ra]=biv.w;
        __syncthreads();

        #pragma unroll 4
        for (int k = 0; k < 16; k++) {
            float4 a_r = *reinterpret_cast<const float4*>(&Asr[k][ty*4]);
            float4 a_i = *reinterpret_cast<const float4*>(&Asi[k][ty*4]);
            float2 b_r = *reinterpret_cast<const float2*>(&Bsr[k][tx*2]);
            float2 b_i = *reinterpret_cast<const float2*>(&Bsi[k][tx*2]);
            const float ar[4] = {a_r.x, a_r.y, a_r.z, a_r.w};
            const float ai[4] = {a_i.x, a_i.y, a_i.z, a_i.w};
            const float wr[2] = {b_r.x, b_r.y};
            const float wi[2] = {b_i.x, b_i.y};
            #pragma unroll
            for (int i = 0; i < 4; i++)
                #pragma unroll
                for (int j = 0; j < 2; j++) {
                    U [i][j] += ar[i] * wr[j];
                    V [i][j] += ai[i] * wi[j];
                    Xc[i][j] += ar[i] * wi[j];
                    Yc[i][j] += ai[i] * wr[j];
                }
        }
        __syncthreads();
    }
    const int gn = n0 + tx*2;
    #pragma unroll
    for (int i = 0; i < 4; i++) {
        const int gm = m0 + ty*4 + i;
        float4 pv = make_float4(U[i][0]-V[i][0], Xc[i][0]+Yc[i][0],
                                U[i][1]-V[i][1], Xc[i][1]+Yc[i][1]);
        float4 qv = make_float4(U[i][0]+V[i][0], Yc[i][0]-Xc[i][0],
                                U[i][1]+V[i][1], Yc[i][1]-Xc[i][1]);
        *reinterpret_cast<float4*>(P + (size_t)gm*HH + gn) = pv;
        *reinterpret_cast<float4*>(Q + (size_t)gm*HH + gn) = qv;
    }
}

// ---- stage 3: pointwise Hermitian-W multiply + cin sum + S/D combine ----
__global__ void k_pointwise(const float* __restrict__ w) {
    const int p = blockIdx.x * blockDim.x + threadIdx.x;  // ky*256+kx
    const int o = blockIdx.y;
    const int ky = p >> 8, kx = p & 255;
    const int ky2 = (N5 - ky) % N5;
    const int kx2 = (N5 - kx) % N5;

    float2 wh1[NCIN], wh2[NCIN];
    #pragma unroll
    for (int c = 0; c < NCIN; c++) {
        const float* wb = w + (size_t)(o*NCIN + c) * PLANE * 2;
        const float2 a = *reinterpret_cast<const float2*>(wb + ((size_t)ky *N5 + kx )*2);
        const float2 bq= *reinterpret_cast<const float2*>(wb + ((size_t)ky2*N5 + kx2)*2);
        wh1[c] = make_float2(0.5f*(a.x + bq.x), 0.5f*(a.y - bq.y));
        if (kx != 0) {
            const float2 e = *reinterpret_cast<const float2*>(wb + ((size_t)ky *N5 + (N5-kx))*2);
            const float2 f = *reinterpret_cast<const float2*>(wb + ((size_t)ky2*N5 + kx     )*2);
            wh2[c] = make_float2(0.5f*(e.x + f.x), 0.5f*(e.y - f.y));
        } else {
            wh2[c] = make_float2(0.f, 0.f);
        }
    }
    #pragma unroll
    for (int b = 0; b < NB; b++) {
        float gr = 0.f, gi = 0.f, hr = 0.f, hi = 0.f;
        #pragma unroll
        for (int c = 0; c < NCIN; c++) {
            const float2 Pv = g_P[(size_t)(b*NCIN + c)*SQ + p];
            const float2 Qv = g_Q[(size_t)(b*NCIN + c)*SQ + p];
            gr += Pv.x * wh1[c].x - Pv.y * wh1[c].y;
            gi += Pv.x * wh1[c].y + Pv.y * wh1[c].x;
            hr += Qv.x * wh2[c].x - Qv.y * wh2[c].y;
            hi += Qv.x * wh2[c].y + Qv.y * wh2[c].x;
        }
        g_SD[(size_t)(b*NCOUT + o)*SQ + p] =
            make_float4(gr + hr, gi + hi, gr - hr, gi - hi);
    }
}

// ---- stage 4 (x-folded, TENSOR): T2 from SD @ {Er,Ei}, K=256, 2xtf32 mma ----
// P=Sr*Er, Q=Di*Ei, R=Si*Er, T=Dr*Ei;  T2[t]=(P-Q, R+T);  T2[257-t]=(P+Q, R-T)
__global__ void __launch_bounds__(128) k_stage4() {
    const int z = blockIdx.z;
    const float4* __restrict__ Ag = g_SD + (size_t)z * SQ;
    float* __restrict__ Cr = g_T2r + (size_t)z * SQ;
    float* __restrict__ Ci = g_T2i + (size_t)z * SQ;

    // A: [chsplit Srh,Srl,Sih,Sil,Drh,Drl,Dih,Dil][k 0..15][m 0..63]; stride 72 = 8 mod 32
    __shared__ float As[8][16][72];
    // B: [chsplit Erh,Erl,Eih,Eil], plane stride 648 words = 8 mod 32; index k*40+n
    __shared__ float Bsm[4 * 648];

    const int tid  = threadIdx.x;
    const int lane = tid & 31, warp = tid >> 5;
    const int g = lane >> 2, c4 = lane & 3;
    const int m0 = blockIdx.y * 64, n0 = blockIdx.x * 32;
    const int wm0 = warp * 16;

    const int lm = tid >> 1, lhalf = tid & 1;      // A loader: row m, k-half
    const int bcs = tid & 3, bn = tid >> 2;        // B loader: chsplit, col n 0..31
    const float* bp = (bcs == 0) ? g_Erh : (bcs == 1) ? g_Erl
                    : (bcs == 2) ? g_Eih : g_Eil;

    float accP[4][4] = {}, accQ[4][4] = {}, accR[4][4] = {}, accT[4][4] = {};

    for (int k0 = 0; k0 < HH; k0 += 16) {
        #pragma unroll
        for (int j = 0; j < 8; j++) {
            const int kk = lhalf * 8 + j;
            float4 v = Ag[(size_t)(m0 + lm) * HH + k0 + kk];
            float h, l;
            split_tf32(v.x, h, l); As[0][kk][lm] = h; As[1][kk][lm] = l;
            split_tf32(v.y, h, l); As[2][kk][lm] = h; As[3][kk][lm] = l;
            split_tf32(v.z, h, l); As[4][kk][lm] = h; As[5][kk][lm] = l;
            split_tf32(v.w, h, l); As[6][kk][lm] = h; As[7][kk][lm] = l;
        }
        #pragma unroll
        for (int j = 0; j < 4; j++) {
            float4 v = *reinterpret_cast<const float4*>(bp + (size_t)(n0 + bn) * HH + k0 + j * 4);
            float* dst = Bsm + bcs * 648;
            dst[(j*4+0)*40 + bn] = v.x;
            dst[(j*4+1)*40 + bn] = v.y;
            dst[(j*4+2)*40 + bn] = v.z;
            dst[(j*4+3)*40 + bn] = v.w;
        }
        __syncthreads();

        #pragma unroll
        for (int ks = 0; ks < 4; ks++) {
            const int kk = ks * 4 + c4;
            unsigned a[8][2];
            #pragma unroll
            for (int cs = 0; cs < 8; cs++) {
                a[cs][0] = __float_as_uint(As[cs][kk][wm0 + g]);
                a[cs][1] = __float_as_uint(As[cs][kk][wm0 + g + 8]);
            }
            #pragma unroll
            for (int ns = 0; ns < 4; ns++) {
                const int bi = kk * 40 + ns * 8 + g;
                unsigned bErh = __float_as_uint(Bsm[0*648 + bi]);
                unsigned bErl = __float_as_uint(Bsm[1*648 + bi]);
                unsigned bEih = __float_as_uint(Bsm[2*648 + bi]);
                unsigned bEil = __float_as_uint(Bsm[3*648 + bi]);
                MMA_TF32_K4(accP[ns], a[0][0], a[0][1], bErh);   // Srh*Erh
                MMA_TF32_K4(accP[ns], a[0][0], a[0][1], bErl);   // Srh*Erl
                MMA_TF32_K4(accP[ns], a[1][0], a[1][1], bErh);   // Srl*Erh
                MMA_TF32_K4(accR[ns], a[2][0], a[2][1], bErh);   // Sih*Erh
                MMA_TF32_K4(accR[ns], a[2][0], a[2][1], bErl);
                MMA_TF32_K4(accR[ns], a[3][0], a[3][1], bErh);
                MMA_TF32_K4(accT[ns], a[4][0], a[4][1], bEih);   // Drh*Eih
                MMA_TF32_K4(accT[ns], a[4][0], a[4][1], bEil);
                MMA_TF32_K4(accT[ns], a[5][0], a[5][1], bEih);
                MMA_TF32_K4(accQ[ns], a[6][0], a[6][1], bEih);   // Dih*Eih
                MMA_TF32_K4(accQ[ns], a[6][0], a[6][1], bEil);
                MMA_TF32_K4(accQ[ns], a[7][0], a[7][1], bEih);
            }
        }
        __syncthreads();
    }
    #pragma unroll
    for (int ns = 0; ns < 4; ns++) {
        #pragma unroll
        for (int e = 0; e < 4; e++) {
            const int gm = m0 + wm0 + g + ((e >> 1) ? 8 : 0);
            const int t  = n0 + ns * 8 + 2 * c4 + (e & 1);
            const float p = accP[ns][e], q = accQ[ns][e];
            const float r = accR[ns][e], tt = accT[ns][e];
            Cr[(size_t)gm * HH + t] = p - q;
            Ci[(size_t)gm * HH + t] = r + tt;
            if (t >= 2) {
                Cr[(size_t)gm * HH + 257 - t] = p + q;
                Ci[(size_t)gm * HH + 257 - t] = r - tt;
            }
        }
    }
}

// ---- stage 4 tail: T2 cols 128,129 from E row 128 (129 = conj partner) ----
__global__ void k_tail4() {
    const int z = blockIdx.y;
    const int warp = threadIdx.x >> 5, lane = threadIdx.x & 31;
    const int ky = blockIdx.x * 8 + warp;
    const float4* __restrict__ Arow = g_SD + (size_t)z * SQ + (size_t)ky * HH;
    float P = 0.f, Q = 0.f, R = 0.f, T = 0.f;
    for (int kx = lane; kx < HH; kx += 32) {
        const float4 a = Arow[kx];
        const float2 e = g_E[128*HH + kx];
        P += a.x * e.x;  Q += a.w * e.y;
        R += a.y * e.x;  T += a.z * e.y;
    }
    #pragma unroll
    for (int off = 16; off; off >>= 1) {
        P += __shfl_down_sync(0xffffffffu, P, off);
        Q += __shfl_down_sync(0xffffffffu, Q, off);
        R += __shfl_down_sync(0xffffffffu, R, off);
        T += __shfl_down_sync(0xffffffffu, T, off);
    }
    if (lane == 0) {
        float* Cr = g_T2r + (size_t)z * SQ + (size_t)ky * HH;
        float* Ci = g_T2i + (size_t)z * SQ + (size_t)ky * HH;
        Cr[128] = P - Q;  Ci[128] = R + T;
        Cr[129] = P + Q;  Ci[129] = R - T;
    }
}

// ---- stage 5 (y-folded): distinct rows y=0..127, partners 257-y (y>=2) ----
__global__ void __launch_bounds__(128) k_stage5(const float* __restrict__ bias,
                                                float* __restrict__ out) {
    const int z = blockIdx.z;
    const float* __restrict__ Br = g_T2r + (size_t)z * SQ;
    const float* __restrict__ Bi = g_T2i + (size_t)z * SQ;
    float* __restrict__ O = out + (size_t)z * SQ;

    __shared__ float Asr[16][36], Asi[16][36], Bsr[16][36], Bsi[16][36];
    const int tid = threadIdx.x;
    const int tx = tid & 15, ty = tid >> 4;
    const int m0 = blockIdx.y * 32, n0 = blockIdx.x * 32;
    const int ra = tid >> 2, ka = (tid & 3) * 4;
    const int kb = tid >> 3, nb = (tid & 7) * 4;

    float P[4][2] = {}, Q[4][2] = {};

    for (int k0 = 0; k0 < HH; k0 += 16) {
        float4 arv = *reinterpret_cast<const float4*>(g_E5r + (size_t)(m0 + ra)*HH + k0 + ka);
        float4 aiv = *reinterpret_cast<const float4*>(g_E5i + (size_t)(m0 + ra)*HH + k0 + ka);
        float4 brv = *reinterpret_cast<const float4*>(Br + (size_t)(k0 + kb)*HH + n0 + nb);
        float4 biv = *reinterpret_cast<const float4*>(Bi + (size_t)(k0 + kb)*HH + n0 + nb);
        Asr[ka+0][ra]=arv.x; Asr[ka+1][ra]=arv.y; Asr[ka+2][ra]=arv.z; Asr[ka+3][ra]=arv.w;
        Asi[ka+0][ra]=aiv.x; Asi[ka+1][ra]=aiv.y; Asi[ka+2][ra]=aiv.z; Asi[ka+3][ra]=aiv.w;
        Bsr[kb][nb+0]=brv.x; Bsr[kb][nb+1]=brv.y; Bsr[kb][nb+2]=brv.z; Bsr[kb][nb+3]=brv.w;
        Bsi[kb][nb+0]=biv.x; Bsi[kb][nb+1]=biv.y; Bsi[kb][nb+2]=biv.z; Bsi[kb][nb+3]=biv.w;
        __syncthreads();

        #pragma unroll 4
        for (int k = 0; k < 16; k++) {
            float4 e_r = *reinterpret_cast<const float4*>(&Asr[k][ty*4]);
            float4 e_i = *reinterpret_cast<const float4*>(&Asi[k][ty*4]);
            float2 b_r = *reinterpret_cast<const float2*>(&Bsr[k][tx*2]);
            float2 b_i = *reinterpret_cast<const float2*>(&Bsi[k][tx*2]);
            const float er[4] = {e_r.x, e_r.y, e_r.z, e_r.w};
            const float ei[4] = {e_i.x, e_i.y, e_i.z, e_i.w};
            const float br[2] = {b_r.x, b_r.y};
            const float bi[2] = {b_i.x, b_i.y};
            #pragma unroll
            for (int i = 0; i < 4; i++)
                #pragma unroll
                for (int j = 0; j < 2; j++) {
                    P[i][j] += er[i] * br[j];
                    Q[i][j] += ei[i] * bi[j];
                }
        }
        __syncthreads();
    }
    const float bv = bias[z & 7];
    const int gn = n0 + tx*2;
    #pragma unroll
    for (int i = 0; i < 4; i++) {
        const int gm = m0 + ty*4 + i;   // 0..127
        *reinterpret_cast<float2*>(&O[(size_t)gm*HH + gn]) =
            make_float2(P[i][0]-Q[i][0] + bv, P[i][1]-Q[i][1] + bv);
        if (gm >= 2) {
            *reinterpret_cast<float2*>(&O[(size_t)(257 - gm)*HH + gn]) =
                make_float2(P[i][0]+Q[i][0] + bv, P[i][1]+Q[i][1] + bv);
        }
    }
}

// ---- stage 5 tail: out rows 128,129 from E5 row 128 (129 = conj partner) ----
__global__ void k_tail5(const float* __restrict__ bias, float* __restrict__ out) {
    const int z = blockIdx.x;
    const int n = threadIdx.x;
    const float* __restrict__ Br = g_T2r + (size_t)z * SQ;
    const float* __restrict__ Bi = g_T2i + (size_t)z * SQ;
    float P = 0.f, Q = 0.f;
    for (int ky = 0; ky < HH; ky++) {
        P += g_E5r[128*HH + ky] * Br[(size_t)ky*HH + n];
        Q += g_E5i[128*HH + ky] * Bi[(size_t)ky*HH + n];
    }
    const float bv = bias[z & 7];
    out[(size_t)z*SQ + 128*HH + n] = P - Q + bv;
    out[(size_t)z*SQ + 129*HH + n] = P + Q + bv;
}

extern "C" void kernel_launch(void* const* d_in, const int* in_sizes, int n_in,
                              void* d_out, int out_size) {
    (void)in_sizes; (void)n_in; (void)out_size;
    const float* im   = (const float*)d_in[0];  // [4,4,256,256]
    const float* w    = (const float*)d_in[1];  // [8,4,511,511,2]
    const float* bias = (const float*)d_in[2];  // [8,1,1]
    float* out = (float*)d_out;                 // [4,8,256,256]

    k_twiddle<<<256, 256>>>();
    k_stage1 <<<dim3(8, 8, BC), 128>>>(im);            // 1024 blocks
    k_stage2 <<<dim3(8, 8, BC), 128>>>();              // 1024 blocks
    k_pointwise<<<dim3(SQ / 256, NCOUT), 256>>>(w);
    k_stage4 <<<dim3(4, 4, BO), 128>>>();              // tensor: 64m x 32n tiles
    k_tail4  <<<dim3(32, BO), 256>>>();                // T2 cols 128,129
    k_stage5 <<<dim3(8, 4, BO), 128>>>(bias, out);     // 1024 blocks, y 0..127
    k_tail5  <<<BO, 256>>>(bias, out);                 // out rows 128,129
}